// round 1
// baseline (speedup 1.0000x reference)
#include <cuda_runtime.h>
#include <math.h>

// ---------------------------------------------------------------------------
// Problem constants (shapes fixed by the dataset: B=8, S=4096)
//   feat: [T=32768, 2048] fp32   (T*2048 elems)
//   w1:   [64, 32], b1: [32], w2: [32], b2: [1]
//   wp:   [1024, 2048], bp: [2048]
//   out:  [T, 2048] fp32
// ---------------------------------------------------------------------------

#define T_MAX 32768

// Scratch: top-16 node indices per token (sorted by descending score).
__device__ int g_topk[T_MAX * 16];

// Monotonic orderable key for a float (total order matching numeric order).
__device__ __forceinline__ unsigned fkey(float x) {
    unsigned u = __float_as_uint(x);
    return (u & 0x80000000u) ? ~u : (u | 0x80000000u);
}

// ---------------------------------------------------------------------------
// Kernel 1: per-token scores + top-16 selection (softmax is order-preserving
// and its values are unused -> skip it entirely).
// One warp per token, one node per lane.
// ---------------------------------------------------------------------------
__global__ void k_score_topk(const float* __restrict__ feat,
                             const float* __restrict__ w1,
                             const float* __restrict__ b1,
                             const float* __restrict__ w2,
                             const float* __restrict__ b2,
                             int* __restrict__ topk, int T)
{
    __shared__ float w1s[32][64];   // transposed: w1s[j][d] = w1[d][j]
    __shared__ float b1s[32];
    __shared__ float w2s[32];
    __shared__ float b2s;

    int tid = threadIdx.x;
    for (int i = tid; i < 2048; i += 256) {
        int j = i >> 6;       // 0..31
        int d = i & 63;       // 0..63
        w1s[j][d] = w1[d * 32 + j];
    }
    if (tid < 32) { b1s[tid] = b1[tid]; w2s[tid] = w2[tid]; }
    if (tid == 0) b2s = b2[0];
    __syncthreads();

    int warp = tid >> 5;
    int lane = tid & 31;
    int t = blockIdx.x * 8 + warp;
    if (t >= T) return;

    // Load this lane's node (64 contiguous floats) into registers.
    float nd[64];
    const float4* np =
        reinterpret_cast<const float4*>(feat + (size_t)t * 2048 + lane * 64);
    #pragma unroll
    for (int i = 0; i < 16; i++) {
        float4 v = np[i];
        nd[4 * i + 0] = v.x; nd[4 * i + 1] = v.y;
        nd[4 * i + 2] = v.z; nd[4 * i + 3] = v.w;
    }

    // score = (gelu(node @ w1 + b1)) @ w2 + b2   (exact GELU, fp32)
    float sc = b2s;
    for (int j = 0; j < 32; j++) {
        float acc = b1s[j];
        #pragma unroll
        for (int d = 0; d < 64; d++) acc = fmaf(nd[d], w1s[j][d], acc);
        float g = 0.5f * acc * (1.0f + erff(acc * 0.7071067811865476f));
        sc = fmaf(g, w2s[j], sc);
    }

    // Top-16 by descending score; ties -> lower node index (jax top_k order).
    unsigned key = fkey(sc);
    int myrank = -1;
    for (int it = 0; it < 16; it++) {
        unsigned long long kv =
            ((unsigned long long)key << 6) | (unsigned)(63 - lane);
        #pragma unroll
        for (int off = 16; off; off >>= 1) {
            unsigned long long o = __shfl_xor_sync(0xffffffffu, kv, off);
            if (o > kv) kv = o;
        }
        int win = 63 - (int)(kv & 63ull);
        if (lane == win) { myrank = it; key = 0u; }  // retire winner
    }
    if (myrank >= 0) topk[t * 16 + myrank] = lane;
}

// ---------------------------------------------------------------------------
// Kernel 2: fused gather + GEMM:
//   out[m, n] = sum_p P[m, p] * wp[p, n] + bp[n]
// where P[m, s*64+d] = feat[m, topk[m][s]*64 + d].
// Tile: BM=128 x BN=64, BK=32 (half of one gathered node segment).
// 256 threads, each computes 8(M) x 4(N) outputs with packed fma.rn.f32x2
// (acc lanes = adjacent M rows; B staged duplicated so both lanes load
// directly via LDS.128).
// ---------------------------------------------------------------------------
#define BM 128
#define BN 64
#define BK 32
#define AS_STRIDE 132   // [k][m], 16B-aligned rows, 2-way store conflicts only
#define BS_STRIDE 136   // [k][2n] duplicated pairs, 16B-aligned rows

__device__ __forceinline__ void ffma2(unsigned long long& d,
                                      unsigned long long a,
                                      unsigned long long b) {
    asm volatile("fma.rn.f32x2 %0, %1, %2, %0;" : "+l"(d) : "l"(a), "l"(b));
}

__global__ void __launch_bounds__(256, 2)
k_gemm(const float* __restrict__ feat,
       const float* __restrict__ wp,
       const float* __restrict__ bp,
       const int* __restrict__ topk,
       float* __restrict__ out, int T)
{
    __shared__ float As[BK][AS_STRIDE];
    __shared__ float Bs[BK][BS_STRIDE];

    int tid = threadIdx.x;
    int m0 = blockIdx.y * BM;
    int n0 = blockIdx.x * BN;

    int tx = tid & 15;   // N group: cols n0 + tx*4 .. +3
    int ty = tid >> 4;   // M group: rows m0 + ty*8 .. +7

    unsigned long long acc[4][4];
    #pragma unroll
    for (int i = 0; i < 4; i++)
        #pragma unroll
        for (int j = 0; j < 4; j++) acc[i][j] = 0ull;

    int lrow  = tid >> 1;   // 0..127, A-load row
    int lpart = tid & 1;    // which 16-float half of the 32-float chunk

    for (int c = 0; c < 32; c++) {          // 32 K-chunks of 32
        int p0 = c * BK;
        int s  = c >> 1;                    // topk slot (64-wide)
        int h  = c & 1;                     // which half of the node segment

        // --- load A tile (gathered) -> As[k][m] ---
        {
            int m = m0 + lrow;
            int idxv = topk[m * 16 + s];
            const float4* ap = reinterpret_cast<const float4*>(
                feat + (size_t)m * 2048 + idxv * 64 + h * 32) + lpart * 4;
            #pragma unroll
            for (int i = 0; i < 4; i++) {
                float4 v = ap[i];
                int f = lpart * 16 + i * 4;
                As[f + 0][lrow] = v.x;
                As[f + 1][lrow] = v.y;
                As[f + 2][lrow] = v.z;
                As[f + 3][lrow] = v.w;
            }
        }

        // --- load B tile -> Bs[k][2n] (each value duplicated) ---
        #pragma unroll
        for (int itB = 0; itB < 2; itB++) {
            int lin = itB * 256 + tid;      // 0..511
            int kk = lin >> 4;              // 0..31
            int f  = lin & 15;              // float4 index within 64 cols
            float4 v = *reinterpret_cast<const float4*>(
                wp + (size_t)(p0 + kk) * 2048 + n0 + f * 4);
            float2* dst = reinterpret_cast<float2*>(&Bs[kk][(f * 4) * 2]);
            dst[0] = make_float2(v.x, v.x);
            dst[1] = make_float2(v.y, v.y);
            dst[2] = make_float2(v.z, v.z);
            dst[3] = make_float2(v.w, v.w);
        }
        __syncthreads();

        // --- MMA inner loop ---
        #pragma unroll 8
        for (int k = 0; k < BK; k++) {
            unsigned long long a2[4], b2v[4];
            const unsigned long long* arow =
                reinterpret_cast<const unsigned long long*>(&As[k][ty * 8]);
            a2[0] = arow[0]; a2[1] = arow[1]; a2[2] = arow[2]; a2[3] = arow[3];
            const unsigned long long* brow =
                reinterpret_cast<const unsigned long long*>(&Bs[k][tx * 8]);
            b2v[0] = brow[0]; b2v[1] = brow[1]; b2v[2] = brow[2]; b2v[3] = brow[3];
            #pragma unroll
            for (int mi = 0; mi < 4; mi++)
                #pragma unroll
                for (int j = 0; j < 4; j++)
                    ffma2(acc[mi][j], a2[mi], b2v[j]);
        }
        __syncthreads();
    }

    // --- epilogue: add bias, store ---
    float bv[4];
    *reinterpret_cast<float4*>(bv) =
        *reinterpret_cast<const float4*>(bp + n0 + tx * 4);

    #pragma unroll
    for (int mi = 0; mi < 4; mi++) {
        int r0 = m0 + ty * 8 + mi * 2;
        float2 a0 = *reinterpret_cast<float2*>(&acc[mi][0]);
        float2 a1 = *reinterpret_cast<float2*>(&acc[mi][1]);
        float2 a2 = *reinterpret_cast<float2*>(&acc[mi][2]);
        float2 a3 = *reinterpret_cast<float2*>(&acc[mi][3]);
        float4 v0 = make_float4(a0.x + bv[0], a1.x + bv[1],
                                a2.x + bv[2], a3.x + bv[3]);
        float4 v1 = make_float4(a0.y + bv[0], a1.y + bv[1],
                                a2.y + bv[2], a3.y + bv[3]);
        *reinterpret_cast<float4*>(out + (size_t)r0 * 2048 + n0 + tx * 4) = v0;
        *reinterpret_cast<float4*>(out + (size_t)(r0 + 1) * 2048 + n0 + tx * 4) = v1;
    }
}

// ---------------------------------------------------------------------------
// Launch
// ---------------------------------------------------------------------------
extern "C" void kernel_launch(void* const* d_in, const int* in_sizes, int n_in,
                              void* d_out, int out_size)
{
    const float* feat = (const float*)d_in[0];
    const float* w1   = (const float*)d_in[1];
    const float* b1   = (const float*)d_in[2];
    const float* w2   = (const float*)d_in[3];
    const float* b2   = (const float*)d_in[4];
    const float* wp   = (const float*)d_in[5];
    const float* bp   = (const float*)d_in[6];
    float* out = (float*)d_out;

    int T = in_sizes[0] / 2048;   // 32768

    int* topk = nullptr;
    cudaGetSymbolAddress((void**)&topk, g_topk);

    // K1: scores + top-16 indices
    k_score_topk<<<(T + 7) / 8, 256>>>(feat, w1, b1, w2, b2, topk, T);

    // K2: gather + GEMM + bias
    dim3 grid(2048 / BN, T / BM);
    k_gemm<<<grid, 256>>>(feat, wp, bp, topk, out, T);
}

// round 3
// speedup vs baseline: 4.6351x; 4.6351x over previous
#include <cuda_runtime.h>
#include <cuda_bf16.h>
#include <math.h>
#include <stdint.h>

// ---------------------------------------------------------------------------
// feat [T=32768, 2048] f32; w1[64,32] b1[32] w2[32,1] b2[1];
// wp [1024, 2048] f32; bp [2048]; out [T, 2048] f32.
//   K1: score MLP + top-16 (softmax monotonic; values unused) -> emits gathered
//       P rows as bf16 hi/lo (fused gather + split)
//   KW: wp -> W_T [2048,1024] bf16 hi/lo (K-major)
//   KG: pipelined mma.sync bf16 GEMM, 3-term split (hh + hl + lh), fp32 accum
//       (base-target ISA only: ldmatrix/mma.sync/cp.async — NO tcgen05)
// ---------------------------------------------------------------------------

#define T_MAX 32768

__device__ __nv_bfloat16 g_Phi[T_MAX * 1024];   // 64 MB
__device__ __nv_bfloat16 g_Plo[T_MAX * 1024];   // 64 MB
__device__ __nv_bfloat16 g_WhiT[2048 * 1024];   // 4 MB  [N,K]
__device__ __nv_bfloat16 g_WloT[2048 * 1024];   // 4 MB  [N,K]

__device__ __forceinline__ uint32_t smem_u32(const void* p) {
    uint32_t a;
    asm("{ .reg .u64 t; cvta.to.shared.u64 t, %1; cvt.u32.u64 %0, t; }"
        : "=r"(a) : "l"(p));
    return a;
}

// ---------------------------------------------------------------------------
// K1: scores + top-16 + fused gather/bf16-split emission. Warp per token.
// ---------------------------------------------------------------------------
__device__ __forceinline__ unsigned fkey(float x) {
    unsigned u = __float_as_uint(x);
    return (u & 0x80000000u) ? ~u : (u | 0x80000000u);
}

__global__ void k_score_topk(const float* __restrict__ feat,
                             const float* __restrict__ w1,
                             const float* __restrict__ b1,
                             const float* __restrict__ w2,
                             const float* __restrict__ b2, int T)
{
    __shared__ float w1s[32][64];
    __shared__ float b1s[32];
    __shared__ float w2s[32];
    __shared__ float b2s;

    int tid = threadIdx.x;
    for (int i = tid; i < 2048; i += 256)
        w1s[i >> 6][i & 63] = w1[(i & 63) * 32 + (i >> 6)];
    if (tid < 32) { b1s[tid] = b1[tid]; w2s[tid] = w2[tid]; }
    if (tid == 0) b2s = b2[0];
    __syncthreads();

    int warp = tid >> 5, lane = tid & 31;
    int t = blockIdx.x * 8 + warp;
    if (t >= T) return;

    float nd[64];
    const float4* np =
        reinterpret_cast<const float4*>(feat + (size_t)t * 2048 + lane * 64);
    #pragma unroll
    for (int i = 0; i < 16; i++) {
        float4 v = np[i];
        nd[4*i] = v.x; nd[4*i+1] = v.y; nd[4*i+2] = v.z; nd[4*i+3] = v.w;
    }

    float sc = b2s;
    for (int j = 0; j < 32; j++) {
        float acc = b1s[j];
        #pragma unroll
        for (int d = 0; d < 64; d++) acc = fmaf(nd[d], w1s[j][d], acc);
        float g = 0.5f * acc * (1.0f + erff(acc * 0.7071067811865476f));
        sc = fmaf(g, w2s[j], sc);
    }

    // top-16 (desc score, tie -> lower index == jax.lax.top_k order)
    unsigned key = fkey(sc);
    int myrank = -1;
    for (int it = 0; it < 16; it++) {
        unsigned long long kv =
            ((unsigned long long)key << 6) | (unsigned)(63 - lane);
        #pragma unroll
        for (int off = 16; off; off >>= 1) {
            unsigned long long o = __shfl_xor_sync(0xffffffffu, kv, off);
            if (o > kv) kv = o;
        }
        int win = 63 - (int)(kv & 63ull);
        if (lane == win) { myrank = it; key = 0u; }
    }

    if (myrank >= 0) {
        size_t base = ((size_t)t * 16 + myrank) * 64;
        uint4* ph = reinterpret_cast<uint4*>(g_Phi + base);
        uint4* pl = reinterpret_cast<uint4*>(g_Plo + base);
        #pragma unroll
        for (int i = 0; i < 8; i++) {
            unsigned hw[4], lw[4];
            #pragma unroll
            for (int j = 0; j < 4; j++) {
                float a = nd[i*8 + j*2], b = nd[i*8 + j*2 + 1];
                __nv_bfloat16 ha = __float2bfloat16(a), hb = __float2bfloat16(b);
                float ra = a - __bfloat162float(ha);
                float rb = b - __bfloat162float(hb);
                __nv_bfloat16 la = __float2bfloat16(ra), lb = __float2bfloat16(rb);
                hw[j] = (unsigned)__bfloat16_as_ushort(ha) |
                        ((unsigned)__bfloat16_as_ushort(hb) << 16);
                lw[j] = (unsigned)__bfloat16_as_ushort(la) |
                        ((unsigned)__bfloat16_as_ushort(lb) << 16);
            }
            ph[i] = make_uint4(hw[0], hw[1], hw[2], hw[3]);
            pl[i] = make_uint4(lw[0], lw[1], lw[2], lw[3]);
        }
    }
}

// ---------------------------------------------------------------------------
// KW: wp [1024,2048] -> W_T [2048,1024] bf16 hi/lo
// ---------------------------------------------------------------------------
__global__ void k_wconv(const float* __restrict__ wp)
{
    int lin = blockIdx.x * 256 + threadIdx.x;
    int n = lin >> 10, k = lin & 1023;
    float x = wp[(size_t)k * 2048 + n];
    __nv_bfloat16 h = __float2bfloat16(x);
    g_WhiT[lin] = h;
    g_WloT[lin] = __float2bfloat16(x - __bfloat162float(h));
}

// ---------------------------------------------------------------------------
// KG: mma.sync bf16 GEMM. CTA tile 128x128, BK=64, 8 warps (64x32 each),
// cp.async 3-stage pipeline, XOR-swizzled smem for conflict-free ldmatrix.
// 3 passes per k-chunk: Ahi*Bhi + Ahi*Blo + Alo*Bhi.
// ---------------------------------------------------------------------------
#define STAGE_BYTES 65536           // Ahi 16K | Alo 16K | Bhi 16K | Blo 16K
#define SMEM_TOTAL (3 * STAGE_BYTES)

__device__ __forceinline__ uint32_t swz(uint32_t base, int row, int k8) {
    // row stride 128B; 16B chunks xor'd with row&7 -> conflict-free ldmatrix
    return base + row * 128 + (((k8 ^ (row & 7)) << 4));
}
__device__ __forceinline__ void cp16(uint32_t s, const void* g) {
    asm volatile("cp.async.cg.shared.global [%0], [%1], 16;"
                 :: "r"(s), "l"(g));
}
#define CP_COMMIT() asm volatile("cp.async.commit_group;" ::: "memory")
#define CP_WAIT2()  asm volatile("cp.async.wait_group 2;"  ::: "memory")

__device__ __forceinline__ void ldmx4(uint32_t* r, uint32_t a) {
    asm volatile("ldmatrix.sync.aligned.m8n8.x4.shared.b16 {%0,%1,%2,%3}, [%4];"
                 : "=r"(r[0]), "=r"(r[1]), "=r"(r[2]), "=r"(r[3]) : "r"(a));
}
__device__ __forceinline__ void mma16816(float* c, const uint32_t* a,
                                         const uint32_t* b) {
    asm volatile(
        "mma.sync.aligned.m16n8k16.row.col.f32.bf16.bf16.f32 "
        "{%0,%1,%2,%3},{%4,%5,%6,%7},{%8,%9},{%0,%1,%2,%3};"
        : "+f"(c[0]), "+f"(c[1]), "+f"(c[2]), "+f"(c[3])
        : "r"(a[0]), "r"(a[1]), "r"(a[2]), "r"(a[3]), "r"(b[0]), "r"(b[1]));
}

__device__ __forceinline__ void load_stage(uint32_t sbase, int m0, int n0,
                                           int c, int tid) {
    const uint4* Ph = reinterpret_cast<const uint4*>(g_Phi);
    const uint4* Pl = reinterpret_cast<const uint4*>(g_Plo);
    const uint4* Wh = reinterpret_cast<const uint4*>(g_WhiT);
    const uint4* Wl = reinterpret_cast<const uint4*>(g_WloT);
    #pragma unroll
    for (int i = 0; i < 4; i++) {
        int lin = i * 256 + tid;            // 0..1023
        int row = lin >> 3, k8 = lin & 7;   // row 0..127, 16B chunk 0..7
        size_t gA = (size_t)(m0 + row) * 128 + c * 8 + k8;  // uint4 units
        size_t gB = (size_t)(n0 + row) * 128 + c * 8 + k8;
        cp16(swz(sbase,          row, k8), Ph + gA);
        cp16(swz(sbase + 16384,  row, k8), Pl + gA);
        cp16(swz(sbase + 32768,  row, k8), Wh + gB);
        cp16(swz(sbase + 49152,  row, k8), Wl + gB);
    }
}

__global__ void __launch_bounds__(256, 1)
k_gemm_mma(const float* __restrict__ bp, float* __restrict__ out)
{
    extern __shared__ char smem[];
    uint32_t sb = smem_u32(smem);
    int tid = threadIdx.x, wid = tid >> 5, lane = tid & 31;
    int n0 = blockIdx.x * 128;
    int m0 = blockIdx.y * 128;
    int wm0 = (wid & 1) * 64;
    int wn0 = (wid >> 1) * 32;

    float acc[4][4][4];
    #pragma unroll
    for (int a = 0; a < 4; a++)
        #pragma unroll
        for (int b = 0; b < 4; b++)
            #pragma unroll
            for (int q = 0; q < 4; q++) acc[a][b][q] = 0.f;

    load_stage(sb,               m0, n0, 0, tid); CP_COMMIT();
    load_stage(sb + STAGE_BYTES, m0, n0, 1, tid); CP_COMMIT();

    // per-lane ldmatrix address components
    int arow = wm0 + (lane & 15);                       // + mt*16
    int ak8 = (lane >> 4);                              // + ks*2
    int brow = wn0 + ((lane >> 4) << 3) + (lane & 7);   // + nt2*16
    int bk8 = (lane >> 3) & 1;                          // + ks*2

    for (int c = 0; c < 16; c++) {
        uint32_t st = sb + (c % 3) * STAGE_BYTES;
        if (c + 2 < 16)
            load_stage(sb + ((c + 2) % 3) * STAGE_BYTES, m0, n0, c + 2, tid);
        CP_COMMIT();            // empty group at tail keeps count invariant
        CP_WAIT2();
        __syncthreads();

        uint32_t Ah = st, Al = st + 16384, Bh = st + 32768, Bl = st + 49152;
        #pragma unroll
        for (int ks = 0; ks < 4; ks++) {
            uint32_t ah[4][4], al[4][4], bh[2][4], bl[2][4];
            #pragma unroll
            for (int mt = 0; mt < 4; mt++) {
                ldmx4(ah[mt], swz(Ah, arow + mt * 16, ks * 2 + ak8));
                ldmx4(al[mt], swz(Al, arow + mt * 16, ks * 2 + ak8));
            }
            #pragma unroll
            for (int nt2 = 0; nt2 < 2; nt2++) {
                ldmx4(bh[nt2], swz(Bh, brow + nt2 * 16, ks * 2 + bk8));
                ldmx4(bl[nt2], swz(Bl, brow + nt2 * 16, ks * 2 + bk8));
            }
            #pragma unroll
            for (int mt = 0; mt < 4; mt++)
                #pragma unroll
                for (int nt = 0; nt < 4; nt++) {
                    const uint32_t* bhp = &bh[nt >> 1][(nt & 1) * 2];
                    const uint32_t* blp = &bl[nt >> 1][(nt & 1) * 2];
                    mma16816(acc[mt][nt], ah[mt], bhp);
                    mma16816(acc[mt][nt], ah[mt], blp);
                    mma16816(acc[mt][nt], al[mt], bhp);
                }
        }
        __syncthreads();
    }

    // epilogue: c-fragment layout -> +bias -> float2 stores
    int tg = lane >> 2, t4 = lane & 3;
    #pragma unroll
    for (int mt = 0; mt < 4; mt++) {
        #pragma unroll
        for (int nt = 0; nt < 4; nt++) {
            int col = n0 + wn0 + nt * 8 + t4 * 2;
            float2 b2 = *reinterpret_cast<const float2*>(bp + col);
            int r0 = m0 + wm0 + mt * 16 + tg;
            float2 v0 = make_float2(acc[mt][nt][0] + b2.x,
                                    acc[mt][nt][1] + b2.y);
            float2 v1 = make_float2(acc[mt][nt][2] + b2.x,
                                    acc[mt][nt][3] + b2.y);
            *reinterpret_cast<float2*>(out + (size_t)r0 * 2048 + col) = v0;
            *reinterpret_cast<float2*>(out + (size_t)(r0 + 8) * 2048 + col) = v1;
        }
    }
}

// ---------------------------------------------------------------------------
// Launch
// ---------------------------------------------------------------------------
extern "C" void kernel_launch(void* const* d_in, const int* in_sizes, int n_in,
                              void* d_out, int out_size)
{
    const float* feat = (const float*)d_in[0];
    const float* w1   = (const float*)d_in[1];
    const float* b1   = (const float*)d_in[2];
    const float* w2   = (const float*)d_in[3];
    const float* b2   = (const float*)d_in[4];
    const float* wp   = (const float*)d_in[5];
    const float* bp   = (const float*)d_in[6];
    float* out = (float*)d_out;

    int T = in_sizes[0] / 2048;   // 32768

    cudaFuncSetAttribute(k_gemm_mma,
                         cudaFuncAttributeMaxDynamicSharedMemorySize, SMEM_TOTAL);

    k_score_topk<<<(T + 7) / 8, 256>>>(feat, w1, b1, w2, b2, T);
    k_wconv<<<(1024 * 2048) / 256, 256>>>(wp);
    dim3 grid(2048 / 128, T / 128);   // N fastest -> A rows L2-resident
    k_gemm_mma<<<grid, 256, SMEM_TOTAL>>>(bp, out);
}

// round 5
// speedup vs baseline: 5.7467x; 1.2398x over previous
#include <cuda_runtime.h>
#include <cuda_fp16.h>
#include <math.h>
#include <stdint.h>

// ---------------------------------------------------------------------------
// feat [T=32768, 2048] f32; w1[64,32] b1[32] w2[32,1] b2[1];
// wp [1024, 2048] f32; bp [2048]; out [T, 2048] f32.
//   K1: score MLP + top-16 (softmax monotonic; values unused). Score math is
//       BIT-IDENTICAL to the twice-validated serial fmaf chain (rank-flip
//       safety). Winning lanes emit gathered P rows as fp16.
//   KW: wp -> W_T [2048,1024] fp16 hi + (residual*1024) fp16 (K-major)
//   KG: pipelined mma.sync fp16 GEMM, 2 passes into separate fp32 accumulator
//       banks: acc_h += A*Whi ; acc_l += A*Wlo_scaled ; out = acc_h+acc_l/1024.
// ---------------------------------------------------------------------------

#define T_MAX 32768

__device__ __half g_Phi[T_MAX * 1024];    // 64 MB   [M,K]
__device__ __half g_WhiT[2048 * 1024];    // 4 MB    [N,K]
__device__ __half g_WloT[2048 * 1024];    // 4 MB    [N,K] residual * 1024

__device__ __forceinline__ uint32_t smem_u32(const void* p) {
    uint32_t a;
    asm("{ .reg .u64 t; cvta.to.shared.u64 t, %1; cvt.u32.u64 %0, t; }"
        : "=r"(a) : "l"(p));
    return a;
}

// ---------------------------------------------------------------------------
// K1: scores + top-16 + fused gather/fp16 emission. Warp per token.
// ---------------------------------------------------------------------------
__device__ __forceinline__ unsigned fkey(float x) {
    unsigned u = __float_as_uint(x);
    return (u & 0x80000000u) ? ~u : (u | 0x80000000u);
}

__global__ void k_score_topk(const float* __restrict__ feat,
                             const float* __restrict__ w1,
                             const float* __restrict__ b1,
                             const float* __restrict__ w2,
                             const float* __restrict__ b2, int T)
{
    __shared__ float4 w1s[32][16];   // row j = w1[:,j] as 16 float4
    __shared__ float b1s[32];
    __shared__ float w2s[32];
    __shared__ float b2s;

    int tid = threadIdx.x;
    for (int i = tid; i < 2048; i += 256) {
        int j = i >> 6, d = i & 63;
        reinterpret_cast<float*>(&w1s[j][0])[d] = w1[d * 32 + j];
    }
    if (tid < 32) { b1s[tid] = b1[tid]; w2s[tid] = w2[tid]; }
    if (tid == 0) b2s = b2[0];
    __syncthreads();

    int warp = tid >> 5, lane = tid & 31;
    int t = blockIdx.x * 8 + warp;
    if (t >= T) return;

    float4 nd[16];
    const float4* np =
        reinterpret_cast<const float4*>(feat + (size_t)t * 2048 + lane * 64);
    #pragma unroll
    for (int i = 0; i < 16; i++) nd[i] = np[i];

    // Serial fmaf chain, EXACT same rounding order as the validated kernel:
    // acc starts at b1s[j], then d = 0..63 in order.
    float sc = b2s;
    for (int j = 0; j < 32; j++) {
        float acc = b1s[j];
        #pragma unroll
        for (int q = 0; q < 16; q++) {
            float4 w = w1s[j][q];
            acc = fmaf(nd[q].x, w.x, acc);
            acc = fmaf(nd[q].y, w.y, acc);
            acc = fmaf(nd[q].z, w.z, acc);
            acc = fmaf(nd[q].w, w.w, acc);
        }
        float g = 0.5f * acc * (1.0f + erff(acc * 0.7071067811865476f));
        sc = fmaf(g, w2s[j], sc);
    }

    // top-16 (desc score, tie -> lower index == jax.lax.top_k order)
    unsigned key = fkey(sc);
    int myrank = -1;
    for (int it = 0; it < 16; it++) {
        unsigned long long kv =
            ((unsigned long long)key << 6) | (unsigned)(63 - lane);
        #pragma unroll
        for (int off = 16; off; off >>= 1) {
            unsigned long long o = __shfl_xor_sync(0xffffffffu, kv, off);
            if (o > kv) kv = o;
        }
        int win = 63 - (int)(kv & 63ull);
        if (lane == win) { myrank = it; key = 0u; }
    }

    if (myrank >= 0) {
        size_t base = ((size_t)t * 16 + myrank) * 64;
        uint4* ph = reinterpret_cast<uint4*>(g_Phi + base);
        const float* ndf = reinterpret_cast<const float*>(nd);
        #pragma unroll
        for (int i = 0; i < 8; i++) {
            unsigned hw[4];
            #pragma unroll
            for (int j = 0; j < 4; j++) {
                __half ha = __float2half_rn(ndf[i*8 + j*2]);
                __half hb = __float2half_rn(ndf[i*8 + j*2 + 1]);
                hw[j] = (unsigned)__half_as_ushort(ha) |
                        ((unsigned)__half_as_ushort(hb) << 16);
            }
            ph[i] = make_uint4(hw[0], hw[1], hw[2], hw[3]);
        }
    }
}

// ---------------------------------------------------------------------------
// KW: wp [1024,2048] -> W_T [2048,1024] fp16 hi + residual*1024 (normal range)
// ---------------------------------------------------------------------------
__global__ void k_wconv(const float* __restrict__ wp)
{
    int lin = blockIdx.x * 256 + threadIdx.x;
    int n = lin >> 10, k = lin & 1023;
    float x = wp[(size_t)k * 2048 + n];
    __half h = __float2half_rn(x);
    g_WhiT[lin] = h;
    g_WloT[lin] = __float2half_rn((x - __half2float(h)) * 1024.0f);
}

// ---------------------------------------------------------------------------
// KG: mma.sync fp16 GEMM. CTA 128x128, BK=64, 8 warps (64x32 each),
// cp.async 3-stage pipeline, XOR-swizzled smem.
// Dual accumulator banks: acc_h (A*Whi), acc_l (A*Wlo_scaled).
// ---------------------------------------------------------------------------
#define STAGE_BYTES 49152           // A 16K | Whi 16K | Wlo 16K
#define SMEM_TOTAL (3 * STAGE_BYTES)

__device__ __forceinline__ uint32_t swz(uint32_t base, int row, int k8) {
    return base + row * 128 + (((k8 ^ (row & 7)) << 4));
}
__device__ __forceinline__ void cp16(uint32_t s, const void* g) {
    asm volatile("cp.async.cg.shared.global [%0], [%1], 16;" :: "r"(s), "l"(g));
}
#define CP_COMMIT() asm volatile("cp.async.commit_group;" ::: "memory")
#define CP_WAIT2()  asm volatile("cp.async.wait_group 2;"  ::: "memory")

__device__ __forceinline__ void ldmx4(uint32_t* r, uint32_t a) {
    asm volatile("ldmatrix.sync.aligned.m8n8.x4.shared.b16 {%0,%1,%2,%3}, [%4];"
                 : "=r"(r[0]), "=r"(r[1]), "=r"(r[2]), "=r"(r[3]) : "r"(a));
}
__device__ __forceinline__ void mma16816(float* c, const uint32_t* a,
                                         const uint32_t* b) {
    asm volatile(
        "mma.sync.aligned.m16n8k16.row.col.f32.f16.f16.f32 "
        "{%0,%1,%2,%3},{%4,%5,%6,%7},{%8,%9},{%0,%1,%2,%3};"
        : "+f"(c[0]), "+f"(c[1]), "+f"(c[2]), "+f"(c[3])
        : "r"(a[0]), "r"(a[1]), "r"(a[2]), "r"(a[3]), "r"(b[0]), "r"(b[1]));
}

__device__ __forceinline__ void load_stage(uint32_t sbase, int m0, int n0,
                                           int c, int tid) {
    const uint4* Ph = reinterpret_cast<const uint4*>(g_Phi);
    const uint4* Wh = reinterpret_cast<const uint4*>(g_WhiT);
    const uint4* Wl = reinterpret_cast<const uint4*>(g_WloT);
    #pragma unroll
    for (int i = 0; i < 4; i++) {
        int lin = i * 256 + tid;            // 0..1023
        int row = lin >> 3, k8 = lin & 7;
        size_t gA = (size_t)(m0 + row) * 128 + c * 8 + k8;
        size_t gB = (size_t)(n0 + row) * 128 + c * 8 + k8;
        cp16(swz(sbase,          row, k8), Ph + gA);
        cp16(swz(sbase + 16384,  row, k8), Wh + gB);
        cp16(swz(sbase + 32768,  row, k8), Wl + gB);
    }
}

__global__ void __launch_bounds__(256, 1)
k_gemm_mma(const float* __restrict__ bp, float* __restrict__ out)
{
    extern __shared__ char smem[];
    uint32_t sb = smem_u32(smem);
    int tid = threadIdx.x, wid = tid >> 5, lane = tid & 31;
    int n0 = blockIdx.x * 128;
    int m0 = blockIdx.y * 128;
    int wm0 = (wid & 1) * 64;
    int wn0 = (wid >> 1) * 32;

    float acc_h[4][4][4], acc_l[4][4][4];
    #pragma unroll
    for (int a = 0; a < 4; a++)
        #pragma unroll
        for (int b = 0; b < 4; b++)
            #pragma unroll
            for (int q = 0; q < 4; q++) { acc_h[a][b][q] = 0.f; acc_l[a][b][q] = 0.f; }

    load_stage(sb,               m0, n0, 0, tid); CP_COMMIT();
    load_stage(sb + STAGE_BYTES, m0, n0, 1, tid); CP_COMMIT();

    int arow = wm0 + (lane & 15);
    int ak8 = (lane >> 4);
    int brow = wn0 + ((lane >> 4) << 3) + (lane & 7);
    int bk8 = (lane >> 3) & 1;

    for (int c = 0; c < 16; c++) {
        uint32_t st = sb + (c % 3) * STAGE_BYTES;
        if (c + 2 < 16)
            load_stage(sb + ((c + 2) % 3) * STAGE_BYTES, m0, n0, c + 2, tid);
        CP_COMMIT();
        CP_WAIT2();
        __syncthreads();

        uint32_t Ah = st, Bh = st + 16384, Bl = st + 32768;
        #pragma unroll
        for (int ks = 0; ks < 4; ks++) {
            uint32_t ah[4][4], bh[2][4], bl[2][4];
            #pragma unroll
            for (int mt = 0; mt < 4; mt++)
                ldmx4(ah[mt], swz(Ah, arow + mt * 16, ks * 2 + ak8));
            #pragma unroll
            for (int nt2 = 0; nt2 < 2; nt2++) {
                ldmx4(bh[nt2], swz(Bh, brow + nt2 * 16, ks * 2 + bk8));
                ldmx4(bl[nt2], swz(Bl, brow + nt2 * 16, ks * 2 + bk8));
            }
            #pragma unroll
            for (int mt = 0; mt < 4; mt++)
                #pragma unroll
                for (int nt = 0; nt < 4; nt++) {
                    const uint32_t* bhp = &bh[nt >> 1][(nt & 1) * 2];
                    const uint32_t* blp = &bl[nt >> 1][(nt & 1) * 2];
                    mma16816(acc_h[mt][nt], ah[mt], bhp);
                    mma16816(acc_l[mt][nt], ah[mt], blp);
                }
        }
        __syncthreads();
    }

    const float RS = 1.0f / 1024.0f;
    int tg = lane >> 2, t4 = lane & 3;
    #pragma unroll
    for (int mt = 0; mt < 4; mt++) {
        #pragma unroll
        for (int nt = 0; nt < 4; nt++) {
            int col = n0 + wn0 + nt * 8 + t4 * 2;
            float2 b2 = *reinterpret_cast<const float2*>(bp + col);
            int r0 = m0 + wm0 + mt * 16 + tg;
            float2 v0, v1;
            v0.x = fmaf(acc_l[mt][nt][0], RS, acc_h[mt][nt][0]) + b2.x;
            v0.y = fmaf(acc_l[mt][nt][1], RS, acc_h[mt][nt][1]) + b2.y;
            v1.x = fmaf(acc_l[mt][nt][2], RS, acc_h[mt][nt][2]) + b2.x;
            v1.y = fmaf(acc_l[mt][nt][3], RS, acc_h[mt][nt][3]) + b2.y;
            *reinterpret_cast<float2*>(out + (size_t)r0 * 2048 + col) = v0;
            *reinterpret_cast<float2*>(out + (size_t)(r0 + 8) * 2048 + col) = v1;
        }
    }
}

// ---------------------------------------------------------------------------
// Launch
// ---------------------------------------------------------------------------
extern "C" void kernel_launch(void* const* d_in, const int* in_sizes, int n_in,
                              void* d_out, int out_size)
{
    const float* feat = (const float*)d_in[0];
    const float* w1   = (const float*)d_in[1];
    const float* b1   = (const float*)d_in[2];
    const float* w2   = (const float*)d_in[3];
    const float* b2   = (const float*)d_in[4];
    const float* wp   = (const float*)d_in[5];
    const float* bp   = (const float*)d_in[6];
    float* out = (float*)d_out;

    int T = in_sizes[0] / 2048;   // 32768

    cudaFuncSetAttribute(k_gemm_mma,
                         cudaFuncAttributeMaxDynamicSharedMemorySize, SMEM_TOTAL);

    k_score_topk<<<(T + 7) / 8, 256>>>(feat, w1, b1, w2, b2, T);
    k_wconv<<<(1024 * 2048) / 256, 256>>>(wp);
    dim3 grid(2048 / 128, T / 128);   // N fastest -> A rows L2-resident
    k_gemm_mma<<<grid, 256, SMEM_TOTAL>>>(bp, out);
}

// round 6
// speedup vs baseline: 9.0603x; 1.5766x over previous
#include <cuda_runtime.h>
#include <cuda_fp16.h>
#include <math.h>
#include <stdint.h>

// ---------------------------------------------------------------------------
// feat [T=32768, 2048] f32; w1[64,32] b1[32] w2[32,1] b2[1];
// wp [1024, 2048] f32; bp [2048]; out [T, 2048] f32.
//   K1: score MLP + top-16 (softmax monotonic; values unused). Score math is
//       BIT-IDENTICAL serial fmaf chain (rank-flip safety); j-loop unrolled
//       for ILP only. Winning lanes emit gathered P rows as fp16.
//   KW: wp -> W_T [2048,1024] fp16 (K-major)
//   KG: pipelined mma.sync fp16 GEMM, SINGLE pass (error ~2.9e-4 << 1e-3),
//       3-stage cp.async, 2 CTAs/SM.
// ---------------------------------------------------------------------------

#define T_MAX 32768

__device__ __half g_Phi[T_MAX * 1024];    // 64 MB   [M,K]
__device__ __half g_WT[2048 * 1024];      // 4 MB    [N,K]

__device__ __forceinline__ uint32_t smem_u32(const void* p) {
    uint32_t a;
    asm("{ .reg .u64 t; cvta.to.shared.u64 t, %1; cvt.u32.u64 %0, t; }"
        : "=r"(a) : "l"(p));
    return a;
}

// ---------------------------------------------------------------------------
// K1: scores + top-16 + fused gather/fp16 emission. Warp per token.
// ---------------------------------------------------------------------------
__device__ __forceinline__ unsigned fkey(float x) {
    unsigned u = __float_as_uint(x);
    return (u & 0x80000000u) ? ~u : (u | 0x80000000u);
}

__global__ void k_score_topk(const float* __restrict__ feat,
                             const float* __restrict__ w1,
                             const float* __restrict__ b1,
                             const float* __restrict__ w2,
                             const float* __restrict__ b2, int T)
{
    __shared__ float4 w1s[32][16];   // row j = w1[:,j] as 16 float4
    __shared__ float b1s[32];
    __shared__ float w2s[32];
    __shared__ float b2s;

    int tid = threadIdx.x;
    for (int i = tid; i < 2048; i += 256) {
        int j = i >> 6, d = i & 63;
        reinterpret_cast<float*>(&w1s[j][0])[d] = w1[d * 32 + j];
    }
    if (tid < 32) { b1s[tid] = b1[tid]; w2s[tid] = w2[tid]; }
    if (tid == 0) b2s = b2[0];
    __syncthreads();

    int warp = tid >> 5, lane = tid & 31;
    int t = blockIdx.x * 8 + warp;
    if (t >= T) return;

    float4 nd[16];
    const float4* np =
        reinterpret_cast<const float4*>(feat + (size_t)t * 2048 + lane * 64);
    #pragma unroll
    for (int i = 0; i < 16; i++) nd[i] = np[i];

    // Serial fmaf chain per j (validated rounding order). Unroll only adds
    // ILP across independent j-chains; each chain's op order is unchanged.
    float sc = b2s;
    #pragma unroll 4
    for (int j = 0; j < 32; j++) {
        float acc = b1s[j];
        #pragma unroll
        for (int q = 0; q < 16; q++) {
            float4 w = w1s[j][q];
            acc = fmaf(nd[q].x, w.x, acc);
            acc = fmaf(nd[q].y, w.y, acc);
            acc = fmaf(nd[q].z, w.z, acc);
            acc = fmaf(nd[q].w, w.w, acc);
        }
        float g = 0.5f * acc * (1.0f + erff(acc * 0.7071067811865476f));
        sc = fmaf(g, w2s[j], sc);
    }

    // top-16 (desc score, tie -> lower index == jax.lax.top_k order)
    unsigned key = fkey(sc);
    int myrank = -1;
    for (int it = 0; it < 16; it++) {
        unsigned long long kv =
            ((unsigned long long)key << 6) | (unsigned)(63 - lane);
        #pragma unroll
        for (int off = 16; off; off >>= 1) {
            unsigned long long o = __shfl_xor_sync(0xffffffffu, kv, off);
            if (o > kv) kv = o;
        }
        int win = 63 - (int)(kv & 63ull);
        if (lane == win) { myrank = it; key = 0u; }
    }

    if (myrank >= 0) {
        size_t base = ((size_t)t * 16 + myrank) * 64;
        uint4* ph = reinterpret_cast<uint4*>(g_Phi + base);
        const float* ndf = reinterpret_cast<const float*>(nd);
        #pragma unroll
        for (int i = 0; i < 8; i++) {
            unsigned hw[4];
            #pragma unroll
            for (int j = 0; j < 4; j++) {
                __half ha = __float2half_rn(ndf[i*8 + j*2]);
                __half hb = __float2half_rn(ndf[i*8 + j*2 + 1]);
                hw[j] = (unsigned)__half_as_ushort(ha) |
                        ((unsigned)__half_as_ushort(hb) << 16);
            }
            ph[i] = make_uint4(hw[0], hw[1], hw[2], hw[3]);
        }
    }
}

// ---------------------------------------------------------------------------
// KW: wp [1024,2048] -> W_T [2048,1024] fp16
// ---------------------------------------------------------------------------
__global__ void k_wconv(const float* __restrict__ wp)
{
    int lin = blockIdx.x * 256 + threadIdx.x;
    int n = lin >> 10, k = lin & 1023;
    g_WT[lin] = __float2half_rn(wp[(size_t)k * 2048 + n]);
}

// ---------------------------------------------------------------------------
// KG: mma.sync fp16 GEMM, single pass. CTA 128x128, BK=64, 8 warps (64x32),
// cp.async 3-stage pipeline, XOR-swizzled smem, 2 CTAs/SM.
// ---------------------------------------------------------------------------
#define STAGE_BYTES 32768           // A 16K | W 16K
#define SMEM_TOTAL (3 * STAGE_BYTES)

__device__ __forceinline__ uint32_t swz(uint32_t base, int row, int k8) {
    return base + row * 128 + (((k8 ^ (row & 7)) << 4));
}
__device__ __forceinline__ void cp16(uint32_t s, const void* g) {
    asm volatile("cp.async.cg.shared.global [%0], [%1], 16;" :: "r"(s), "l"(g));
}
#define CP_COMMIT() asm volatile("cp.async.commit_group;" ::: "memory")
#define CP_WAIT2()  asm volatile("cp.async.wait_group 2;"  ::: "memory")

__device__ __forceinline__ void ldmx4(uint32_t* r, uint32_t a) {
    asm volatile("ldmatrix.sync.aligned.m8n8.x4.shared.b16 {%0,%1,%2,%3}, [%4];"
                 : "=r"(r[0]), "=r"(r[1]), "=r"(r[2]), "=r"(r[3]) : "r"(a));
}
__device__ __forceinline__ void mma16816(float* c, const uint32_t* a,
                                         const uint32_t* b) {
    asm volatile(
        "mma.sync.aligned.m16n8k16.row.col.f32.f16.f16.f32 "
        "{%0,%1,%2,%3},{%4,%5,%6,%7},{%8,%9},{%0,%1,%2,%3};"
        : "+f"(c[0]), "+f"(c[1]), "+f"(c[2]), "+f"(c[3])
        : "r"(a[0]), "r"(a[1]), "r"(a[2]), "r"(a[3]), "r"(b[0]), "r"(b[1]));
}

__device__ __forceinline__ void load_stage(uint32_t sbase, int m0, int n0,
                                           int c, int tid) {
    const uint4* Ph = reinterpret_cast<const uint4*>(g_Phi);
    const uint4* Wh = reinterpret_cast<const uint4*>(g_WT);
    #pragma unroll
    for (int i = 0; i < 4; i++) {
        int lin = i * 256 + tid;            // 0..1023
        int row = lin >> 3, k8 = lin & 7;
        size_t gA = (size_t)(m0 + row) * 128 + c * 8 + k8;
        size_t gB = (size_t)(n0 + row) * 128 + c * 8 + k8;
        cp16(swz(sbase,          row, k8), Ph + gA);
        cp16(swz(sbase + 16384,  row, k8), Wh + gB);
    }
}

__global__ void __launch_bounds__(256, 2)
k_gemm_mma(const float* __restrict__ bp, float* __restrict__ out)
{
    extern __shared__ char smem[];
    uint32_t sb = smem_u32(smem);
    int tid = threadIdx.x, wid = tid >> 5, lane = tid & 31;
    int n0 = blockIdx.x * 128;
    int m0 = blockIdx.y * 128;
    int wm0 = (wid & 1) * 64;
    int wn0 = (wid >> 1) * 32;

    float acc[4][4][4];
    #pragma unroll
    for (int a = 0; a < 4; a++)
        #pragma unroll
        for (int b = 0; b < 4; b++)
            #pragma unroll
            for (int q = 0; q < 4; q++) acc[a][b][q] = 0.f;

    load_stage(sb,               m0, n0, 0, tid); CP_COMMIT();
    load_stage(sb + STAGE_BYTES, m0, n0, 1, tid); CP_COMMIT();

    int arow = wm0 + (lane & 15);
    int ak8 = (lane >> 4);
    int brow = wn0 + ((lane >> 4) << 3) + (lane & 7);
    int bk8 = (lane >> 3) & 1;

    for (int c = 0; c < 16; c++) {
        uint32_t st = sb + (c % 3) * STAGE_BYTES;
        if (c + 2 < 16)
            load_stage(sb + ((c + 2) % 3) * STAGE_BYTES, m0, n0, c + 2, tid);
        CP_COMMIT();
        CP_WAIT2();
        __syncthreads();

        uint32_t Ah = st, Bh = st + 16384;
        #pragma unroll
        for (int ks = 0; ks < 4; ks++) {
            uint32_t ah[4][4], bh[2][4];
            #pragma unroll
            for (int mt = 0; mt < 4; mt++)
                ldmx4(ah[mt], swz(Ah, arow + mt * 16, ks * 2 + ak8));
            #pragma unroll
            for (int nt2 = 0; nt2 < 2; nt2++)
                ldmx4(bh[nt2], swz(Bh, brow + nt2 * 16, ks * 2 + bk8));
            #pragma unroll
            for (int mt = 0; mt < 4; mt++)
                #pragma unroll
                for (int nt = 0; nt < 4; nt++)
                    mma16816(acc[mt][nt], ah[mt], &bh[nt >> 1][(nt & 1) * 2]);
        }
        __syncthreads();
    }

    int tg = lane >> 2, t4 = lane & 3;
    #pragma unroll
    for (int mt = 0; mt < 4; mt++) {
        #pragma unroll
        for (int nt = 0; nt < 4; nt++) {
            int col = n0 + wn0 + nt * 8 + t4 * 2;
            float2 b2 = *reinterpret_cast<const float2*>(bp + col);
            int r0 = m0 + wm0 + mt * 16 + tg;
            float2 v0 = make_float2(acc[mt][nt][0] + b2.x,
                                    acc[mt][nt][1] + b2.y);
            float2 v1 = make_float2(acc[mt][nt][2] + b2.x,
                                    acc[mt][nt][3] + b2.y);
            *reinterpret_cast<float2*>(out + (size_t)r0 * 2048 + col) = v0;
            *reinterpret_cast<float2*>(out + (size_t)(r0 + 8) * 2048 + col) = v1;
        }
    }
}

// ---------------------------------------------------------------------------
// Launch
// ---------------------------------------------------------------------------
extern "C" void kernel_launch(void* const* d_in, const int* in_sizes, int n_in,
                              void* d_out, int out_size)
{
    const float* feat = (const float*)d_in[0];
    const float* w1   = (const float*)d_in[1];
    const float* b1   = (const float*)d_in[2];
    const float* w2   = (const float*)d_in[3];
    const float* b2   = (const float*)d_in[4];
    const float* wp   = (const float*)d_in[5];
    const float* bp   = (const float*)d_in[6];
    float* out = (float*)d_out;

    int T = in_sizes[0] / 2048;   // 32768

    cudaFuncSetAttribute(k_gemm_mma,
                         cudaFuncAttributeMaxDynamicSharedMemorySize, SMEM_TOTAL);

    k_score_topk<<<(T + 7) / 8, 256>>>(feat, w1, b1, w2, b2, T);
    k_wconv<<<(1024 * 2048) / 256, 256>>>(wp);
    dim3 grid(2048 / 128, T / 128);   // N fastest -> A rows L2-resident
    k_gemm_mma<<<grid, 256, SMEM_TOTAL>>>(bp, out);
}